// round 9
// baseline (speedup 1.0000x reference)
#include <cuda_runtime.h>

#define D_MODEL  1024
#define N_HEADS  16
#define HEAD_DIM 64
#define SEQ      2048
#define BATCH    2
#define M_ROWS   (BATCH * SEQ)   // 4096

// Scratch (device globals: allocation-free per harness rules)
__device__ float g_q[M_ROWS * D_MODEL];
__device__ float g_k[M_ROWS * D_MODEL];
__device__ float g_v[M_ROWS * D_MODEL];
__device__ float g_y[M_ROWS * D_MODEL];

// ---------------------------------------------------------------------------
// NT GEMM: Y = X @ W^T + bias.   X:[M,K], W:[N,K], bias:[N]
// splitHeads==1: write Y into [B,H,T,Dh] layout (fused split_heads)
// splitHeads==0: write Y row-major [M,N]
// Tiles: 128x128x8, 256 threads, 8x8 per thread, double-buffered SMEM.
// ---------------------------------------------------------------------------
__global__ void __launch_bounds__(256) sgemm_nt(
    const float* __restrict__ X, const float* __restrict__ W,
    const float* __restrict__ bias, float* __restrict__ Y,
    int M, int N, int K, int splitHeads)
{
    __shared__ float As[2][8][128];
    __shared__ float Bs[2][8][128];

    const int tid = threadIdx.x;
    const int tx  = tid & 15;          // 0..15 (n groups)
    const int ty  = tid >> 4;          // 0..15 (m groups)
    const int m0  = blockIdx.y * 128;
    const int n0  = blockIdx.x * 128;

    // global-load mapping: 128 rows x 8 k-cols per operand, 1 float4/thread
    const int lrow = tid >> 1;         // 0..127
    const int lseg = (tid & 1) * 4;    // 0 or 4

    const float* Xp = X + (m0 + lrow) * K + lseg;
    const float* Wp = W + (n0 + lrow) * K + lseg;

    float4 xa = *(const float4*)Xp;
    float4 wb = *(const float4*)Wp;

    As[0][lseg + 0][lrow] = xa.x;
    As[0][lseg + 1][lrow] = xa.y;
    As[0][lseg + 2][lrow] = xa.z;
    As[0][lseg + 3][lrow] = xa.w;
    Bs[0][lseg + 0][lrow] = wb.x;
    Bs[0][lseg + 1][lrow] = wb.y;
    Bs[0][lseg + 2][lrow] = wb.z;
    Bs[0][lseg + 3][lrow] = wb.w;
    __syncthreads();

    float acc[8][8];
#pragma unroll
    for (int i = 0; i < 8; ++i)
#pragma unroll
        for (int j = 0; j < 8; ++j) acc[i][j] = 0.0f;

    const int ntiles = K >> 3;
    int buf = 0;
    for (int t = 0; t < ntiles; ++t) {
        if (t + 1 < ntiles) {
            xa = *(const float4*)(Xp + (t + 1) * 8);
            wb = *(const float4*)(Wp + (t + 1) * 8);
        }
#pragma unroll
        for (int k = 0; k < 8; ++k) {
            float4 a0 = *(const float4*)(&As[buf][k][ty * 4]);
            float4 a1 = *(const float4*)(&As[buf][k][ty * 4 + 64]);
            float4 b0 = *(const float4*)(&Bs[buf][k][tx * 4]);
            float4 b1 = *(const float4*)(&Bs[buf][k][tx * 4 + 64]);
            float a[8] = {a0.x, a0.y, a0.z, a0.w, a1.x, a1.y, a1.z, a1.w};
            float b[8] = {b0.x, b0.y, b0.z, b0.w, b1.x, b1.y, b1.z, b1.w};
#pragma unroll
            for (int i = 0; i < 8; ++i)
#pragma unroll
                for (int j = 0; j < 8; ++j)
                    acc[i][j] += a[i] * b[j];
        }
        if (t + 1 < ntiles) {
            buf ^= 1;
            As[buf][lseg + 0][lrow] = xa.x;
            As[buf][lseg + 1][lrow] = xa.y;
            As[buf][lseg + 2][lrow] = xa.z;
            As[buf][lseg + 3][lrow] = xa.w;
            Bs[buf][lseg + 0][lrow] = wb.x;
            Bs[buf][lseg + 1][lrow] = wb.y;
            Bs[buf][lseg + 2][lrow] = wb.z;
            Bs[buf][lseg + 3][lrow] = wb.w;
            __syncthreads();
        }
    }

    // epilogue
#pragma unroll
    for (int ih = 0; ih < 2; ++ih) {
#pragma unroll
        for (int r = 0; r < 4; ++r) {
            const int m = m0 + ih * 64 + ty * 4 + r;
#pragma unroll
            for (int jh = 0; jh < 2; ++jh) {
                const int n = n0 + jh * 64 + tx * 4;
                float4 v;
                v.x = acc[ih * 4 + r][jh * 4 + 0] + bias[n + 0];
                v.y = acc[ih * 4 + r][jh * 4 + 1] + bias[n + 1];
                v.z = acc[ih * 4 + r][jh * 4 + 2] + bias[n + 2];
                v.w = acc[ih * 4 + r][jh * 4 + 3] + bias[n + 3];
                if (splitHeads) {
                    const int b  = m >> 11;          // m / SEQ
                    const int tt = m & (SEQ - 1);
                    const int h  = n >> 6;           // n / HEAD_DIM
                    const int d  = n & (HEAD_DIM - 1);
                    *(float4*)(Y + ((b * N_HEADS + h) * SEQ + tt) * HEAD_DIM + d) = v;
                } else {
                    *(float4*)(Y + m * N + n) = v;
                }
            }
        }
    }
}

// ---------------------------------------------------------------------------
// Flash attention, causal. Q/K/V in [B*H, T, Dh] layout.
// One CTA = 64 query rows of one (b,h). 256 threads: thread (i,j) owns a
// 4x4 block (rows i*4.., cols/dims j*4..). Online softmax; P staged
// transposed through SMEM for the PV product. Output -> [B,T,C].
// ---------------------------------------------------------------------------
#define AP 68   // SMEM row pitch (floats) = 17 float4s, kills stride-64 conflicts

__global__ void __launch_bounds__(256) attn_kernel(
    const float* __restrict__ Q, const float* __restrict__ K,
    const float* __restrict__ V, float* __restrict__ Y)
{
    extern __shared__ float sm[];
    float* Qs = sm;                 // [d][m]
    float* Ks = sm + 64 * AP;       // [d][n]
    float* Vs = sm + 2 * 64 * AP;   // [c][d]
    float* Ps = sm + 3 * 64 * AP;   // [c][m]

    const int tid = threadIdx.x;
    const int i   = tid >> 4;       // 0..15 row group
    const int j   = tid & 15;       // 0..15 col group
    const int bh  = blockIdx.y;
    const int qt  = (int)gridDim.x - 1 - (int)blockIdx.x;  // long tiles first

    // load Q tile, transposed to [d][m]
    const float* Qg = Q + (bh * SEQ + qt * 64) * HEAD_DIM;
#pragma unroll
    for (int l = 0; l < 4; ++l) {
        const int e   = tid + l * 256;       // float4 index, 0..1023
        const int row = e >> 4;
        const int d4  = (e & 15) << 2;
        float4 v = *(const float4*)(Qg + row * 64 + d4);
        Qs[(d4 + 0) * AP + row] = v.x;
        Qs[(d4 + 1) * AP + row] = v.y;
        Qs[(d4 + 2) * AP + row] = v.z;
        Qs[(d4 + 3) * AP + row] = v.w;
    }

    float mrow[4], lsum[4], o[4][4];
#pragma unroll
    for (int r = 0; r < 4; ++r) {
        mrow[r] = -1e30f;
        lsum[r] = 0.0f;
#pragma unroll
        for (int c = 0; c < 4; ++c) o[r][c] = 0.0f;
    }

    for (int kt = 0; kt <= qt; ++kt) {
        __syncthreads();   // previous iteration done with Ks/Vs/Ps
        const float* Kg = K + (bh * SEQ + kt * 64) * HEAD_DIM;
        const float* Vg = V + (bh * SEQ + kt * 64) * HEAD_DIM;
#pragma unroll
        for (int l = 0; l < 4; ++l) {
            const int e   = tid + l * 256;
            const int row = e >> 4;
            const int d4  = (e & 15) << 2;
            float4 kv = *(const float4*)(Kg + row * 64 + d4);
            Ks[(d4 + 0) * AP + row] = kv.x;
            Ks[(d4 + 1) * AP + row] = kv.y;
            Ks[(d4 + 2) * AP + row] = kv.z;
            Ks[(d4 + 3) * AP + row] = kv.w;
            *(float4*)(Vs + row * AP + d4) = *(const float4*)(Vg + row * 64 + d4);
        }
        __syncthreads();

        // S = Q K^T  (4x4 per thread)
        float s[4][4];
#pragma unroll
        for (int r = 0; r < 4; ++r)
#pragma unroll
            for (int c = 0; c < 4; ++c) s[r][c] = 0.0f;

#pragma unroll 16
        for (int d = 0; d < 64; ++d) {
            float4 q4 = *(const float4*)(Qs + d * AP + i * 4);
            float4 k4 = *(const float4*)(Ks + d * AP + j * 4);
            float qa[4] = {q4.x, q4.y, q4.z, q4.w};
            float kb[4] = {k4.x, k4.y, k4.z, k4.w};
#pragma unroll
            for (int r = 0; r < 4; ++r)
#pragma unroll
                for (int c = 0; c < 4; ++c)
                    s[r][c] += qa[r] * kb[c];
        }

        const float sc = 0.125f;  // 1/sqrt(64)
        if (kt == qt) {
#pragma unroll
            for (int r = 0; r < 4; ++r)
#pragma unroll
                for (int c = 0; c < 4; ++c)
                    s[r][c] = ((j * 4 + c) <= (i * 4 + r)) ? s[r][c] * sc : -1e30f;
        } else {
#pragma unroll
            for (int r = 0; r < 4; ++r)
#pragma unroll
                for (int c = 0; c < 4; ++c)
                    s[r][c] *= sc;
        }

        // online softmax (row stats reduced over the 16 j-threads)
#pragma unroll
        for (int r = 0; r < 4; ++r) {
            float mx = fmaxf(fmaxf(s[r][0], s[r][1]), fmaxf(s[r][2], s[r][3]));
            mx = fmaxf(mx, __shfl_xor_sync(0xffffffffu, mx, 1));
            mx = fmaxf(mx, __shfl_xor_sync(0xffffffffu, mx, 2));
            mx = fmaxf(mx, __shfl_xor_sync(0xffffffffu, mx, 4));
            mx = fmaxf(mx, __shfl_xor_sync(0xffffffffu, mx, 8));
            const float mn   = fmaxf(mrow[r], mx);
            const float corr = __expf(mrow[r] - mn);
            mrow[r] = mn;
            float rs = 0.0f;
#pragma unroll
            for (int c = 0; c < 4; ++c) {
                float p = __expf(s[r][c] - mn);
                s[r][c] = p;
                rs += p;
            }
            rs += __shfl_xor_sync(0xffffffffu, rs, 1);
            rs += __shfl_xor_sync(0xffffffffu, rs, 2);
            rs += __shfl_xor_sync(0xffffffffu, rs, 4);
            rs += __shfl_xor_sync(0xffffffffu, rs, 8);
            lsum[r] = lsum[r] * corr + rs;
#pragma unroll
            for (int c = 0; c < 4; ++c) o[r][c] *= corr;
        }

        // stage P transposed: Ps[c][m]
#pragma unroll
        for (int c = 0; c < 4; ++c)
#pragma unroll
            for (int r = 0; r < 4; ++r)
                Ps[(j * 4 + c) * AP + i * 4 + r] = s[r][c];
        __syncthreads();

        // O += P V   (rows i*4.., dims j*4..)
#pragma unroll 16
        for (int c = 0; c < 64; ++c) {
            float4 p4 = *(const float4*)(Ps + c * AP + i * 4);
            float4 v4 = *(const float4*)(Vs + c * AP + j * 4);
            float pa[4] = {p4.x, p4.y, p4.z, p4.w};
            float vb[4] = {v4.x, v4.y, v4.z, v4.w};
#pragma unroll
            for (int r = 0; r < 4; ++r)
#pragma unroll
                for (int cc = 0; cc < 4; ++cc)
                    o[r][cc] += pa[r] * vb[cc];
        }
    }

    // write out, merging heads: Y[b, t, h*64 + d]
    const int b = bh >> 4;
    const int h = bh & 15;
#pragma unroll
    for (int r = 0; r < 4; ++r) {
        const float inv = 1.0f / lsum[r];
        const int t = qt * 64 + i * 4 + r;
        float4 outv = make_float4(o[r][0] * inv, o[r][1] * inv,
                                  o[r][2] * inv, o[r][3] * inv);
        *(float4*)(Y + (b * SEQ + t) * D_MODEL + h * 64 + j * 4) = outv;
    }
}

// ---------------------------------------------------------------------------
extern "C" void kernel_launch(void* const* d_in, const int* in_sizes, int n_in,
                              void* d_out, int out_size)
{
    const float* x  = (const float*)d_in[0];
    const float* Wk = (const float*)d_in[1];
    const float* bk = (const float*)d_in[2];
    const float* Wq = (const float*)d_in[3];
    const float* bq = (const float*)d_in[4];
    const float* Wv = (const float*)d_in[5];
    const float* bv = (const float*)d_in[6];
    const float* Wp = (const float*)d_in[7];
    const float* bp = (const float*)d_in[8];

    float *qp, *kp, *vp, *yp;
    cudaGetSymbolAddress((void**)&qp, g_q);
    cudaGetSymbolAddress((void**)&kp, g_k);
    cudaGetSymbolAddress((void**)&vp, g_v);
    cudaGetSymbolAddress((void**)&yp, g_y);

    const int attn_smem = 4 * 64 * AP * (int)sizeof(float);  // 69632 B
    cudaFuncSetAttribute(attn_kernel,
                         cudaFuncAttributeMaxDynamicSharedMemorySize, attn_smem);

    dim3 ggrid(D_MODEL / 128, M_ROWS / 128);   // (8, 32)
    sgemm_nt<<<ggrid, 256>>>(x, Wq, bq, qp, M_ROWS, D_MODEL, D_MODEL, 1);
    sgemm_nt<<<ggrid, 256>>>(x, Wk, bk, kp, M_ROWS, D_MODEL, D_MODEL, 1);
    sgemm_nt<<<ggrid, 256>>>(x, Wv, bv, vp, M_ROWS, D_MODEL, D_MODEL, 1);

    attn_kernel<<<dim3(SEQ / 64, BATCH * N_HEADS), 256, attn_smem>>>(qp, kp, vp, yp);

    sgemm_nt<<<ggrid, 256>>>(yp, Wp, bp, (float*)d_out, M_ROWS, D_MODEL, D_MODEL, 0);
}

// round 10
// speedup vs baseline: 1.0034x; 1.0034x over previous
#include <cuda_runtime.h>

#define D_MODEL  1024
#define N_HEADS  16
#define HEAD_DIM 64
#define SEQ      2048
#define BATCH    2
#define M_ROWS   (BATCH * SEQ)   // 4096

// Scratch (device globals: allocation-free per harness rules)
__device__ float g_q[M_ROWS * D_MODEL];
__device__ float g_k[M_ROWS * D_MODEL];
__device__ float g_v[M_ROWS * D_MODEL];
__device__ float g_y[M_ROWS * D_MODEL];

// ---------------------------------------------------------------------------
// NT GEMM: Y = X @ W^T + bias.   X:[M,K], W:[N,K], bias:[N]
// splitHeads==1: write Y into [B,H,T,Dh] layout (fused split_heads)
// splitHeads==0: write Y row-major [M,N]
// Tiles: 128x128x8, 256 threads, 8x8 per thread, double-buffered SMEM.
// ---------------------------------------------------------------------------
__global__ void __launch_bounds__(256) sgemm_nt(
    const float* __restrict__ X, const float* __restrict__ W,
    const float* __restrict__ bias, float* __restrict__ Y,
    int M, int N, int K, int splitHeads)
{
    __shared__ float As[2][8][128];
    __shared__ float Bs[2][8][128];

    const int tid = threadIdx.x;
    const int tx  = tid & 15;          // 0..15 (n groups)
    const int ty  = tid >> 4;          // 0..15 (m groups)
    const int m0  = blockIdx.y * 128;
    const int n0  = blockIdx.x * 128;

    // global-load mapping: 128 rows x 8 k-cols per operand, 1 float4/thread
    const int lrow = tid >> 1;         // 0..127
    const int lseg = (tid & 1) * 4;    // 0 or 4

    const float* Xp = X + (m0 + lrow) * K + lseg;
    const float* Wp = W + (n0 + lrow) * K + lseg;

    float4 xa = *(const float4*)Xp;
    float4 wb = *(const float4*)Wp;

    As[0][lseg + 0][lrow] = xa.x;
    As[0][lseg + 1][lrow] = xa.y;
    As[0][lseg + 2][lrow] = xa.z;
    As[0][lseg + 3][lrow] = xa.w;
    Bs[0][lseg + 0][lrow] = wb.x;
    Bs[0][lseg + 1][lrow] = wb.y;
    Bs[0][lseg + 2][lrow] = wb.z;
    Bs[0][lseg + 3][lrow] = wb.w;
    __syncthreads();

    float acc[8][8];
#pragma unroll
    for (int i = 0; i < 8; ++i)
#pragma unroll
        for (int j = 0; j < 8; ++j) acc[i][j] = 0.0f;

    const int ntiles = K >> 3;
    int buf = 0;
    for (int t = 0; t < ntiles; ++t) {
        if (t + 1 < ntiles) {
            xa = *(const float4*)(Xp + (t + 1) * 8);
            wb = *(const float4*)(Wp + (t + 1) * 8);
        }
#pragma unroll
        for (int k = 0; k < 8; ++k) {
            float4 a0 = *(const float4*)(&As[buf][k][ty * 4]);
            float4 a1 = *(const float4*)(&As[buf][k][ty * 4 + 64]);
            float4 b0 = *(const float4*)(&Bs[buf][k][tx * 4]);
            float4 b1 = *(const float4*)(&Bs[buf][k][tx * 4 + 64]);
            float a[8] = {a0.x, a0.y, a0.z, a0.w, a1.x, a1.y, a1.z, a1.w};
            float b[8] = {b0.x, b0.y, b0.z, b0.w, b1.x, b1.y, b1.z, b1.w};
#pragma unroll
            for (int i = 0; i < 8; ++i)
#pragma unroll
                for (int j = 0; j < 8; ++j)
                    acc[i][j] += a[i] * b[j];
        }
        if (t + 1 < ntiles) {
            buf ^= 1;
            As[buf][lseg + 0][lrow] = xa.x;
            As[buf][lseg + 1][lrow] = xa.y;
            As[buf][lseg + 2][lrow] = xa.z;
            As[buf][lseg + 3][lrow] = xa.w;
            Bs[buf][lseg + 0][lrow] = wb.x;
            Bs[buf][lseg + 1][lrow] = wb.y;
            Bs[buf][lseg + 2][lrow] = wb.z;
            Bs[buf][lseg + 3][lrow] = wb.w;
            __syncthreads();
        }
    }

    // epilogue
#pragma unroll
    for (int ih = 0; ih < 2; ++ih) {
#pragma unroll
        for (int r = 0; r < 4; ++r) {
            const int m = m0 + ih * 64 + ty * 4 + r;
#pragma unroll
            for (int jh = 0; jh < 2; ++jh) {
                const int n = n0 + jh * 64 + tx * 4;
                float4 v;
                v.x = acc[ih * 4 + r][jh * 4 + 0] + bias[n + 0];
                v.y = acc[ih * 4 + r][jh * 4 + 1] + bias[n + 1];
                v.z = acc[ih * 4 + r][jh * 4 + 2] + bias[n + 2];
                v.w = acc[ih * 4 + r][jh * 4 + 3] + bias[n + 3];
                if (splitHeads) {
                    const int b  = m >> 11;          // m / SEQ
                    const int tt = m & (SEQ - 1);
                    const int h  = n >> 6;           // n / HEAD_DIM
                    const int d  = n & (HEAD_DIM - 1);
                    *(float4*)(Y + ((b * N_HEADS + h) * SEQ + tt) * HEAD_DIM + d) = v;
                } else {
                    *(float4*)(Y + m * N + n) = v;
                }
            }
        }
    }
}

// ---------------------------------------------------------------------------
// Flash attention, causal. Q/K/V in [B*H, T, Dh] layout.
// One CTA = 64 query rows of one (b,h). 256 threads: thread (i,j) owns a
// 4x4 block (rows i*4.., cols/dims j*4..). Online softmax; P staged
// transposed through SMEM for the PV product. Output -> [B,T,C].
// ---------------------------------------------------------------------------
#define AP 68   // SMEM row pitch (floats) = 17 float4s, kills stride-64 conflicts

__global__ void __launch_bounds__(256) attn_kernel(
    const float* __restrict__ Q, const float* __restrict__ K,
    const float* __restrict__ V, float* __restrict__ Y)
{
    extern __shared__ float sm[];
    float* Qs = sm;                 // [d][m]
    float* Ks = sm + 64 * AP;       // [d][n]
    float* Vs = sm + 2 * 64 * AP;   // [c][d]
    float* Ps = sm + 3 * 64 * AP;   // [c][m]

    const int tid = threadIdx.x;
    const int i   = tid >> 4;       // 0..15 row group
    const int j   = tid & 15;       // 0..15 col group
    const int bh  = blockIdx.y;
    const int qt  = (int)gridDim.x - 1 - (int)blockIdx.x;  // long tiles first

    // load Q tile, transposed to [d][m]
    const float* Qg = Q + (bh * SEQ + qt * 64) * HEAD_DIM;
#pragma unroll
    for (int l = 0; l < 4; ++l) {
        const int e   = tid + l * 256;       // float4 index, 0..1023
        const int row = e >> 4;
        const int d4  = (e & 15) << 2;
        float4 v = *(const float4*)(Qg + row * 64 + d4);
        Qs[(d4 + 0) * AP + row] = v.x;
        Qs[(d4 + 1) * AP + row] = v.y;
        Qs[(d4 + 2) * AP + row] = v.z;
        Qs[(d4 + 3) * AP + row] = v.w;
    }

    float mrow[4], lsum[4], o[4][4];
#pragma unroll
    for (int r = 0; r < 4; ++r) {
        mrow[r] = -1e30f;
        lsum[r] = 0.0f;
#pragma unroll
        for (int c = 0; c < 4; ++c) o[r][c] = 0.0f;
    }

    for (int kt = 0; kt <= qt; ++kt) {
        __syncthreads();   // previous iteration done with Ks/Vs/Ps
        const float* Kg = K + (bh * SEQ + kt * 64) * HEAD_DIM;
        const float* Vg = V + (bh * SEQ + kt * 64) * HEAD_DIM;
#pragma unroll
        for (int l = 0; l < 4; ++l) {
            const int e   = tid + l * 256;
            const int row = e >> 4;
            const int d4  = (e & 15) << 2;
            float4 kv = *(const float4*)(Kg + row * 64 + d4);
            Ks[(d4 + 0) * AP + row] = kv.x;
            Ks[(d4 + 1) * AP + row] = kv.y;
            Ks[(d4 + 2) * AP + row] = kv.z;
            Ks[(d4 + 3) * AP + row] = kv.w;
            *(float4*)(Vs + row * AP + d4) = *(const float4*)(Vg + row * 64 + d4);
        }
        __syncthreads();

        // S = Q K^T  (4x4 per thread)
        float s[4][4];
#pragma unroll
        for (int r = 0; r < 4; ++r)
#pragma unroll
            for (int c = 0; c < 4; ++c) s[r][c] = 0.0f;

#pragma unroll 16
        for (int d = 0; d < 64; ++d) {
            float4 q4 = *(const float4*)(Qs + d * AP + i * 4);
            float4 k4 = *(const float4*)(Ks + d * AP + j * 4);
            float qa[4] = {q4.x, q4.y, q4.z, q4.w};
            float kb[4] = {k4.x, k4.y, k4.z, k4.w};
#pragma unroll
            for (int r = 0; r < 4; ++r)
#pragma unroll
                for (int c = 0; c < 4; ++c)
                    s[r][c] += qa[r] * kb[c];
        }

        const float sc = 0.125f;  // 1/sqrt(64)
        if (kt == qt) {
#pragma unroll
            for (int r = 0; r < 4; ++r)
#pragma unroll
                for (int c = 0; c < 4; ++c)
                    s[r][c] = ((j * 4 + c) <= (i * 4 + r)) ? s[r][c] * sc : -1e30f;
        } else {
#pragma unroll
            for (int r = 0; r < 4; ++r)
#pragma unroll
                for (int c = 0; c < 4; ++c)
                    s[r][c] *= sc;
        }

        // online softmax (row stats reduced over the 16 j-threads)
#pragma unroll
        for (int r = 0; r < 4; ++r) {
            float mx = fmaxf(fmaxf(s[r][0], s[r][1]), fmaxf(s[r][2], s[r][3]));
            mx = fmaxf(mx, __shfl_xor_sync(0xffffffffu, mx, 1));
            mx = fmaxf(mx, __shfl_xor_sync(0xffffffffu, mx, 2));
            mx = fmaxf(mx, __shfl_xor_sync(0xffffffffu, mx, 4));
            mx = fmaxf(mx, __shfl_xor_sync(0xffffffffu, mx, 8));
            const float mn   = fmaxf(mrow[r], mx);
            const float corr = __expf(mrow[r] - mn);
            mrow[r] = mn;
            float rs = 0.0f;
#pragma unroll
            for (int c = 0; c < 4; ++c) {
                float p = __expf(s[r][c] - mn);
                s[r][c] = p;
                rs += p;
            }
            rs += __shfl_xor_sync(0xffffffffu, rs, 1);
            rs += __shfl_xor_sync(0xffffffffu, rs, 2);
            rs += __shfl_xor_sync(0xffffffffu, rs, 4);
            rs += __shfl_xor_sync(0xffffffffu, rs, 8);
            lsum[r] = lsum[r] * corr + rs;
#pragma unroll
            for (int c = 0; c < 4; ++c) o[r][c] *= corr;
        }

        // stage P transposed: Ps[c][m]
#pragma unroll
        for (int c = 0; c < 4; ++c)
#pragma unroll
            for (int r = 0; r < 4; ++r)
                Ps[(j * 4 + c) * AP + i * 4 + r] = s[r][c];
        __syncthreads();

        // O += P V   (rows i*4.., dims j*4..)
#pragma unroll 16
        for (int c = 0; c < 64; ++c) {
            float4 p4 = *(const float4*)(Ps + c * AP + i * 4);
            float4 v4 = *(const float4*)(Vs + c * AP + j * 4);
            float pa[4] = {p4.x, p4.y, p4.z, p4.w};
            float vb[4] = {v4.x, v4.y, v4.z, v4.w};
#pragma unroll
            for (int r = 0; r < 4; ++r)
#pragma unroll
                for (int cc = 0; cc < 4; ++cc)
                    o[r][cc] += pa[r] * vb[cc];
        }
    }

    // write out, merging heads: Y[b, t, h*64 + d]
    const int b = bh >> 4;
    const int h = bh & 15;
#pragma unroll
    for (int r = 0; r < 4; ++r) {
        const float inv = 1.0f / lsum[r];
        const int t = qt * 64 + i * 4 + r;
        float4 outv = make_float4(o[r][0] * inv, o[r][1] * inv,
                                  o[r][2] * inv, o[r][3] * inv);
        *(float4*)(Y + (b * SEQ + t) * D_MODEL + h * 64 + j * 4) = outv;
    }
}

// ---------------------------------------------------------------------------
extern "C" void kernel_launch(void* const* d_in, const int* in_sizes, int n_in,
                              void* d_out, int out_size)
{
    const float* x  = (const float*)d_in[0];
    const float* Wk = (const float*)d_in[1];
    const float* bk = (const float*)d_in[2];
    const float* Wq = (const float*)d_in[3];
    const float* bq = (const float*)d_in[4];
    const float* Wv = (const float*)d_in[5];
    const float* bv = (const float*)d_in[6];
    const float* Wp = (const float*)d_in[7];
    const float* bp = (const float*)d_in[8];

    float *qp, *kp, *vp, *yp;
    cudaGetSymbolAddress((void**)&qp, g_q);
    cudaGetSymbolAddress((void**)&kp, g_k);
    cudaGetSymbolAddress((void**)&vp, g_v);
    cudaGetSymbolAddress((void**)&yp, g_y);

    const int attn_smem = 4 * 64 * AP * (int)sizeof(float);  // 69632 B
    cudaFuncSetAttribute(attn_kernel,
                         cudaFuncAttributeMaxDynamicSharedMemorySize, attn_smem);

    dim3 ggrid(D_MODEL / 128, M_ROWS / 128);   // (8, 32)
    sgemm_nt<<<ggrid, 256>>>(x, Wq, bq, qp, M_ROWS, D_MODEL, D_MODEL, 1);
    sgemm_nt<<<ggrid, 256>>>(x, Wk, bk, kp, M_ROWS, D_MODEL, D_MODEL, 1);
    sgemm_nt<<<ggrid, 256>>>(x, Wv, bv, vp, M_ROWS, D_MODEL, D_MODEL, 1);

    attn_kernel<<<dim3(SEQ / 64, BATCH * N_HEADS), 256, attn_smem>>>(qp, kp, vp, yp);

    sgemm_nt<<<ggrid, 256>>>(yp, Wp, bp, (float*)d_out, M_ROWS, D_MODEL, D_MODEL, 0);
}

// round 11
// speedup vs baseline: 1.0077x; 1.0043x over previous
#include <cuda_runtime.h>

#define D_MODEL  1024
#define N_HEADS  16
#define HEAD_DIM 64
#define SEQ      2048
#define BATCH    2
#define M_ROWS   (BATCH * SEQ)   // 4096

// Scratch (device globals: allocation-free per harness rules)
__device__ float g_q[M_ROWS * D_MODEL];
__device__ float g_k[M_ROWS * D_MODEL];
__device__ float g_v[M_ROWS * D_MODEL];
__device__ float g_y[M_ROWS * D_MODEL];

// ---------------------------------------------------------------------------
// NT GEMM: Y = X @ W^T + bias.   X:[M,K], W:[N,K], bias:[N]
// splitHeads==1: write Y into [B,H,T,Dh] layout (fused split_heads)
// splitHeads==0: write Y row-major [M,N]
// Tiles: 128x128x8, 256 threads, 8x8 per thread, double-buffered SMEM.
// ---------------------------------------------------------------------------
__global__ void __launch_bounds__(256) sgemm_nt(
    const float* __restrict__ X, const float* __restrict__ W,
    const float* __restrict__ bias, float* __restrict__ Y,
    int M, int N, int K, int splitHeads)
{
    __shared__ float As[2][8][128];
    __shared__ float Bs[2][8][128];

    const int tid = threadIdx.x;
    const int tx  = tid & 15;          // 0..15 (n groups)
    const int ty  = tid >> 4;          // 0..15 (m groups)
    const int m0  = blockIdx.y * 128;
    const int n0  = blockIdx.x * 128;

    // global-load mapping: 128 rows x 8 k-cols per operand, 1 float4/thread
    const int lrow = tid >> 1;         // 0..127
    const int lseg = (tid & 1) * 4;    // 0 or 4

    const float* Xp = X + (m0 + lrow) * K + lseg;
    const float* Wp = W + (n0 + lrow) * K + lseg;

    float4 xa = *(const float4*)Xp;
    float4 wb = *(const float4*)Wp;

    As[0][lseg + 0][lrow] = xa.x;
    As[0][lseg + 1][lrow] = xa.y;
    As[0][lseg + 2][lrow] = xa.z;
    As[0][lseg + 3][lrow] = xa.w;
    Bs[0][lseg + 0][lrow] = wb.x;
    Bs[0][lseg + 1][lrow] = wb.y;
    Bs[0][lseg + 2][lrow] = wb.z;
    Bs[0][lseg + 3][lrow] = wb.w;
    __syncthreads();

    float acc[8][8];
#pragma unroll
    for (int i = 0; i < 8; ++i)
#pragma unroll
        for (int j = 0; j < 8; ++j) acc[i][j] = 0.0f;

    const int ntiles = K >> 3;
    int buf = 0;
    for (int t = 0; t < ntiles; ++t) {
        if (t + 1 < ntiles) {
            xa = *(const float4*)(Xp + (t + 1) * 8);
            wb = *(const float4*)(Wp + (t + 1) * 8);
        }
#pragma unroll
        for (int k = 0; k < 8; ++k) {
            float4 a0 = *(const float4*)(&As[buf][k][ty * 4]);
            float4 a1 = *(const float4*)(&As[buf][k][ty * 4 + 64]);
            float4 b0 = *(const float4*)(&Bs[buf][k][tx * 4]);
            float4 b1 = *(const float4*)(&Bs[buf][k][tx * 4 + 64]);
            float a[8] = {a0.x, a0.y, a0.z, a0.w, a1.x, a1.y, a1.z, a1.w};
            float b[8] = {b0.x, b0.y, b0.z, b0.w, b1.x, b1.y, b1.z, b1.w};
#pragma unroll
            for (int i = 0; i < 8; ++i)
#pragma unroll
                for (int j = 0; j < 8; ++j)
                    acc[i][j] += a[i] * b[j];
        }
        if (t + 1 < ntiles) {
            buf ^= 1;
            As[buf][lseg + 0][lrow] = xa.x;
            As[buf][lseg + 1][lrow] = xa.y;
            As[buf][lseg + 2][lrow] = xa.z;
            As[buf][lseg + 3][lrow] = xa.w;
            Bs[buf][lseg + 0][lrow] = wb.x;
            Bs[buf][lseg + 1][lrow] = wb.y;
            Bs[buf][lseg + 2][lrow] = wb.z;
            Bs[buf][lseg + 3][lrow] = wb.w;
            __syncthreads();
        }
    }

    // epilogue
#pragma unroll
    for (int ih = 0; ih < 2; ++ih) {
#pragma unroll
        for (int r = 0; r < 4; ++r) {
            const int m = m0 + ih * 64 + ty * 4 + r;
#pragma unroll
            for (int jh = 0; jh < 2; ++jh) {
                const int n = n0 + jh * 64 + tx * 4;
                float4 v;
                v.x = acc[ih * 4 + r][jh * 4 + 0] + bias[n + 0];
                v.y = acc[ih * 4 + r][jh * 4 + 1] + bias[n + 1];
                v.z = acc[ih * 4 + r][jh * 4 + 2] + bias[n + 2];
                v.w = acc[ih * 4 + r][jh * 4 + 3] + bias[n + 3];
                if (splitHeads) {
                    const int b  = m >> 11;          // m / SEQ
                    const int tt = m & (SEQ - 1);
                    const int h  = n >> 6;           // n / HEAD_DIM
                    const int d  = n & (HEAD_DIM - 1);
                    *(float4*)(Y + ((b * N_HEADS + h) * SEQ + tt) * HEAD_DIM + d) = v;
                } else {
                    *(float4*)(Y + m * N + n) = v;
                }
            }
        }
    }
}

// ---------------------------------------------------------------------------
// Flash attention, causal. Q/K/V in [B*H, T, Dh] layout.
// One CTA = 64 query rows of one (b,h). 256 threads: thread (i,j) owns a
// 4x4 block (rows i*4.., cols/dims j*4..). Online softmax; P staged
// transposed through SMEM for the PV product. Output -> [B,T,C].
// ---------------------------------------------------------------------------
#define AP 68   // SMEM row pitch (floats) = 17 float4s, kills stride-64 conflicts

__global__ void __launch_bounds__(256) attn_kernel(
    const float* __restrict__ Q, const float* __restrict__ K,
    const float* __restrict__ V, float* __restrict__ Y)
{
    extern __shared__ float sm[];
    float* Qs = sm;                 // [d][m]
    float* Ks = sm + 64 * AP;       // [d][n]
    float* Vs = sm + 2 * 64 * AP;   // [c][d]
    float* Ps = sm + 3 * 64 * AP;   // [c][m]

    const int tid = threadIdx.x;
    const int i   = tid >> 4;       // 0..15 row group
    const int j   = tid & 15;       // 0..15 col group
    const int bh  = blockIdx.y;
    const int qt  = (int)gridDim.x - 1 - (int)blockIdx.x;  // long tiles first

    // load Q tile, transposed to [d][m]
    const float* Qg = Q + (bh * SEQ + qt * 64) * HEAD_DIM;
#pragma unroll
    for (int l = 0; l < 4; ++l) {
        const int e   = tid + l * 256;       // float4 index, 0..1023
        const int row = e >> 4;
        const int d4  = (e & 15) << 2;
        float4 v = *(const float4*)(Qg + row * 64 + d4);
        Qs[(d4 + 0) * AP + row] = v.x;
        Qs[(d4 + 1) * AP + row] = v.y;
        Qs[(d4 + 2) * AP + row] = v.z;
        Qs[(d4 + 3) * AP + row] = v.w;
    }

    float mrow[4], lsum[4], o[4][4];
#pragma unroll
    for (int r = 0; r < 4; ++r) {
        mrow[r] = -1e30f;
        lsum[r] = 0.0f;
#pragma unroll
        for (int c = 0; c < 4; ++c) o[r][c] = 0.0f;
    }

    for (int kt = 0; kt <= qt; ++kt) {
        __syncthreads();   // previous iteration done with Ks/Vs/Ps
        const float* Kg = K + (bh * SEQ + kt * 64) * HEAD_DIM;
        const float* Vg = V + (bh * SEQ + kt * 64) * HEAD_DIM;
#pragma unroll
        for (int l = 0; l < 4; ++l) {
            const int e   = tid + l * 256;
            const int row = e >> 4;
            const int d4  = (e & 15) << 2;
            float4 kv = *(const float4*)(Kg + row * 64 + d4);
            Ks[(d4 + 0) * AP + row] = kv.x;
            Ks[(d4 + 1) * AP + row] = kv.y;
            Ks[(d4 + 2) * AP + row] = kv.z;
            Ks[(d4 + 3) * AP + row] = kv.w;
            *(float4*)(Vs + row * AP + d4) = *(const float4*)(Vg + row * 64 + d4);
        }
        __syncthreads();

        // S = Q K^T  (4x4 per thread)
        float s[4][4];
#pragma unroll
        for (int r = 0; r < 4; ++r)
#pragma unroll
            for (int c = 0; c < 4; ++c) s[r][c] = 0.0f;

#pragma unroll 16
        for (int d = 0; d < 64; ++d) {
            float4 q4 = *(const float4*)(Qs + d * AP + i * 4);
            float4 k4 = *(const float4*)(Ks + d * AP + j * 4);
            float qa[4] = {q4.x, q4.y, q4.z, q4.w};
            float kb[4] = {k4.x, k4.y, k4.z, k4.w};
#pragma unroll
            for (int r = 0; r < 4; ++r)
#pragma unroll
                for (int c = 0; c < 4; ++c)
                    s[r][c] += qa[r] * kb[c];
        }

        const float sc = 0.125f;  // 1/sqrt(64)
        if (kt == qt) {
#pragma unroll
            for (int r = 0; r < 4; ++r)
#pragma unroll
                for (int c = 0; c < 4; ++c)
                    s[r][c] = ((j * 4 + c) <= (i * 4 + r)) ? s[r][c] * sc : -1e30f;
        } else {
#pragma unroll
            for (int r = 0; r < 4; ++r)
#pragma unroll
                for (int c = 0; c < 4; ++c)
                    s[r][c] *= sc;
        }

        // online softmax (row stats reduced over the 16 j-threads)
#pragma unroll
        for (int r = 0; r < 4; ++r) {
            float mx = fmaxf(fmaxf(s[r][0], s[r][1]), fmaxf(s[r][2], s[r][3]));
            mx = fmaxf(mx, __shfl_xor_sync(0xffffffffu, mx, 1));
            mx = fmaxf(mx, __shfl_xor_sync(0xffffffffu, mx, 2));
            mx = fmaxf(mx, __shfl_xor_sync(0xffffffffu, mx, 4));
            mx = fmaxf(mx, __shfl_xor_sync(0xffffffffu, mx, 8));
            const float mn   = fmaxf(mrow[r], mx);
            const float corr = __expf(mrow[r] - mn);
            mrow[r] = mn;
            float rs = 0.0f;
#pragma unroll
            for (int c = 0; c < 4; ++c) {
                float p = __expf(s[r][c] - mn);
                s[r][c] = p;
                rs += p;
            }
            rs += __shfl_xor_sync(0xffffffffu, rs, 1);
            rs += __shfl_xor_sync(0xffffffffu, rs, 2);
            rs += __shfl_xor_sync(0xffffffffu, rs, 4);
            rs += __shfl_xor_sync(0xffffffffu, rs, 8);
            lsum[r] = lsum[r] * corr + rs;
#pragma unroll
            for (int c = 0; c < 4; ++c) o[r][c] *= corr;
        }

        // stage P transposed: Ps[c][m]
#pragma unroll
        for (int c = 0; c < 4; ++c)
#pragma unroll
            for (int r = 0; r < 4; ++r)
                Ps[(j * 4 + c) * AP + i * 4 + r] = s[r][c];
        __syncthreads();

        // O += P V   (rows i*4.., dims j*4..)
#pragma unroll 16
        for (int c = 0; c < 64; ++c) {
            float4 p4 = *(const float4*)(Ps + c * AP + i * 4);
            float4 v4 = *(const float4*)(Vs + c * AP + j * 4);
            float pa[4] = {p4.x, p4.y, p4.z, p4.w};
            float vb[4] = {v4.x, v4.y, v4.z, v4.w};
#pragma unroll
            for (int r = 0; r < 4; ++r)
#pragma unroll
                for (int cc = 0; cc < 4; ++cc)
                    o[r][cc] += pa[r] * vb[cc];
        }
    }

    // write out, merging heads: Y[b, t, h*64 + d]
    const int b = bh >> 4;
    const int h = bh & 15;
#pragma unroll
    for (int r = 0; r < 4; ++r) {
        const float inv = 1.0f / lsum[r];
        const int t = qt * 64 + i * 4 + r;
        float4 outv = make_float4(o[r][0] * inv, o[r][1] * inv,
                                  o[r][2] * inv, o[r][3] * inv);
        *(float4*)(Y + (b * SEQ + t) * D_MODEL + h * 64 + j * 4) = outv;
    }
}

// ---------------------------------------------------------------------------
extern "C" void kernel_launch(void* const* d_in, const int* in_sizes, int n_in,
                              void* d_out, int out_size)
{
    const float* x  = (const float*)d_in[0];
    const float* Wk = (const float*)d_in[1];
    const float* bk = (const float*)d_in[2];
    const float* Wq = (const float*)d_in[3];
    const float* bq = (const float*)d_in[4];
    const float* Wv = (const float*)d_in[5];
    const float* bv = (const float*)d_in[6];
    const float* Wp = (const float*)d_in[7];
    const float* bp = (const float*)d_in[8];

    float *qp, *kp, *vp, *yp;
    cudaGetSymbolAddress((void**)&qp, g_q);
    cudaGetSymbolAddress((void**)&kp, g_k);
    cudaGetSymbolAddress((void**)&vp, g_v);
    cudaGetSymbolAddress((void**)&yp, g_y);

    const int attn_smem = 4 * 64 * AP * (int)sizeof(float);  // 69632 B
    cudaFuncSetAttribute(attn_kernel,
                         cudaFuncAttributeMaxDynamicSharedMemorySize, attn_smem);

    dim3 ggrid(D_MODEL / 128, M_ROWS / 128);   // (8, 32)
    sgemm_nt<<<ggrid, 256>>>(x, Wq, bq, qp, M_ROWS, D_MODEL, D_MODEL, 1);
    sgemm_nt<<<ggrid, 256>>>(x, Wk, bk, kp, M_ROWS, D_MODEL, D_MODEL, 1);
    sgemm_nt<<<ggrid, 256>>>(x, Wv, bv, vp, M_ROWS, D_MODEL, D_MODEL, 1);

    attn_kernel<<<dim3(SEQ / 64, BATCH * N_HEADS), 256, attn_smem>>>(qp, kp, vp, yp);

    sgemm_nt<<<ggrid, 256>>>(yp, Wp, bp, (float*)d_out, M_ROWS, D_MODEL, D_MODEL, 0);
}

// round 12
// speedup vs baseline: 1.0105x; 1.0028x over previous
#include <cuda_runtime.h>

#define D_MODEL  1024
#define N_HEADS  16
#define HEAD_DIM 64
#define SEQ      2048
#define BATCH    2
#define M_ROWS   (BATCH * SEQ)   // 4096

// Scratch (device globals: allocation-free per harness rules)
__device__ float g_q[M_ROWS * D_MODEL];
__device__ float g_k[M_ROWS * D_MODEL];
__device__ float g_v[M_ROWS * D_MODEL];
__device__ float g_y[M_ROWS * D_MODEL];

// ---------------------------------------------------------------------------
// NT GEMM: Y = X @ W^T + bias.   X:[M,K], W:[N,K], bias:[N]
// splitHeads==1: write Y into [B,H,T,Dh] layout (fused split_heads)
// splitHeads==0: write Y row-major [M,N]
// Tiles: 128x128x8, 256 threads, 8x8 per thread, double-buffered SMEM.
// ---------------------------------------------------------------------------
__global__ void __launch_bounds__(256) sgemm_nt(
    const float* __restrict__ X, const float* __restrict__ W,
    const float* __restrict__ bias, float* __restrict__ Y,
    int M, int N, int K, int splitHeads)
{
    __shared__ float As[2][8][128];
    __shared__ float Bs[2][8][128];

    const int tid = threadIdx.x;
    const int tx  = tid & 15;          // 0..15 (n groups)
    const int ty  = tid >> 4;          // 0..15 (m groups)
    const int m0  = blockIdx.y * 128;
    const int n0  = blockIdx.x * 128;

    // global-load mapping: 128 rows x 8 k-cols per operand, 1 float4/thread
    const int lrow = tid >> 1;         // 0..127
    const int lseg = (tid & 1) * 4;    // 0 or 4

    const float* Xp = X + (m0 + lrow) * K + lseg;
    const float* Wp = W + (n0 + lrow) * K + lseg;

    float4 xa = *(const float4*)Xp;
    float4 wb = *(const float4*)Wp;

    As[0][lseg + 0][lrow] = xa.x;
    As[0][lseg + 1][lrow] = xa.y;
    As[0][lseg + 2][lrow] = xa.z;
    As[0][lseg + 3][lrow] = xa.w;
    Bs[0][lseg + 0][lrow] = wb.x;
    Bs[0][lseg + 1][lrow] = wb.y;
    Bs[0][lseg + 2][lrow] = wb.z;
    Bs[0][lseg + 3][lrow] = wb.w;
    __syncthreads();

    float acc[8][8];
#pragma unroll
    for (int i = 0; i < 8; ++i)
#pragma unroll
        for (int j = 0; j < 8; ++j) acc[i][j] = 0.0f;

    const int ntiles = K >> 3;
    int buf = 0;
    for (int t = 0; t < ntiles; ++t) {
        if (t + 1 < ntiles) {
            xa = *(const float4*)(Xp + (t + 1) * 8);
            wb = *(const float4*)(Wp + (t + 1) * 8);
        }
#pragma unroll
        for (int k = 0; k < 8; ++k) {
            float4 a0 = *(const float4*)(&As[buf][k][ty * 4]);
            float4 a1 = *(const float4*)(&As[buf][k][ty * 4 + 64]);
            float4 b0 = *(const float4*)(&Bs[buf][k][tx * 4]);
            float4 b1 = *(const float4*)(&Bs[buf][k][tx * 4 + 64]);
            float a[8] = {a0.x, a0.y, a0.z, a0.w, a1.x, a1.y, a1.z, a1.w};
            float b[8] = {b0.x, b0.y, b0.z, b0.w, b1.x, b1.y, b1.z, b1.w};
#pragma unroll
            for (int i = 0; i < 8; ++i)
#pragma unroll
                for (int j = 0; j < 8; ++j)
                    acc[i][j] += a[i] * b[j];
        }
        if (t + 1 < ntiles) {
            buf ^= 1;
            As[buf][lseg + 0][lrow] = xa.x;
            As[buf][lseg + 1][lrow] = xa.y;
            As[buf][lseg + 2][lrow] = xa.z;
            As[buf][lseg + 3][lrow] = xa.w;
            Bs[buf][lseg + 0][lrow] = wb.x;
            Bs[buf][lseg + 1][lrow] = wb.y;
            Bs[buf][lseg + 2][lrow] = wb.z;
            Bs[buf][lseg + 3][lrow] = wb.w;
            __syncthreads();
        }
    }

    // epilogue
#pragma unroll
    for (int ih = 0; ih < 2; ++ih) {
#pragma unroll
        for (int r = 0; r < 4; ++r) {
            const int m = m0 + ih * 64 + ty * 4 + r;
#pragma unroll
            for (int jh = 0; jh < 2; ++jh) {
                const int n = n0 + jh * 64 + tx * 4;
                float4 v;
                v.x = acc[ih * 4 + r][jh * 4 + 0] + bias[n + 0];
                v.y = acc[ih * 4 + r][jh * 4 + 1] + bias[n + 1];
                v.z = acc[ih * 4 + r][jh * 4 + 2] + bias[n + 2];
                v.w = acc[ih * 4 + r][jh * 4 + 3] + bias[n + 3];
                if (splitHeads) {
                    const int b  = m >> 11;          // m / SEQ
                    const int tt = m & (SEQ - 1);
                    const int h  = n >> 6;           // n / HEAD_DIM
                    const int d  = n & (HEAD_DIM - 1);
                    *(float4*)(Y + ((b * N_HEADS + h) * SEQ + tt) * HEAD_DIM + d) = v;
                } else {
                    *(float4*)(Y + m * N + n) = v;
                }
            }
        }
    }
}

// ---------------------------------------------------------------------------
// Flash attention, causal. Q/K/V in [B*H, T, Dh] layout.
// One CTA = 64 query rows of one (b,h). 256 threads: thread (i,j) owns a
// 4x4 block (rows i*4.., cols/dims j*4..). Online softmax; P staged
// transposed through SMEM for the PV product. Output -> [B,T,C].
// ---------------------------------------------------------------------------
#define AP 68   // SMEM row pitch (floats) = 17 float4s, kills stride-64 conflicts

__global__ void __launch_bounds__(256) attn_kernel(
    const float* __restrict__ Q, const float* __restrict__ K,
    const float* __restrict__ V, float* __restrict__ Y)
{
    extern __shared__ float sm[];
    float* Qs = sm;                 // [d][m]
    float* Ks = sm + 64 * AP;       // [d][n]
    float* Vs = sm + 2 * 64 * AP;   // [c][d]
    float* Ps = sm + 3 * 64 * AP;   // [c][m]

    const int tid = threadIdx.x;
    const int i   = tid >> 4;       // 0..15 row group
    const int j   = tid & 15;       // 0..15 col group
    const int bh  = blockIdx.y;
    const int qt  = (int)gridDim.x - 1 - (int)blockIdx.x;  // long tiles first

    // load Q tile, transposed to [d][m]
    const float* Qg = Q + (bh * SEQ + qt * 64) * HEAD_DIM;
#pragma unroll
    for (int l = 0; l < 4; ++l) {
        const int e   = tid + l * 256;       // float4 index, 0..1023
        const int row = e >> 4;
        const int d4  = (e & 15) << 2;
        float4 v = *(const float4*)(Qg + row * 64 + d4);
        Qs[(d4 + 0) * AP + row] = v.x;
        Qs[(d4 + 1) * AP + row] = v.y;
        Qs[(d4 + 2) * AP + row] = v.z;
        Qs[(d4 + 3) * AP + row] = v.w;
    }

    float mrow[4], lsum[4], o[4][4];
#pragma unroll
    for (int r = 0; r < 4; ++r) {
        mrow[r] = -1e30f;
        lsum[r] = 0.0f;
#pragma unroll
        for (int c = 0; c < 4; ++c) o[r][c] = 0.0f;
    }

    for (int kt = 0; kt <= qt; ++kt) {
        __syncthreads();   // previous iteration done with Ks/Vs/Ps
        const float* Kg = K + (bh * SEQ + kt * 64) * HEAD_DIM;
        const float* Vg = V + (bh * SEQ + kt * 64) * HEAD_DIM;
#pragma unroll
        for (int l = 0; l < 4; ++l) {
            const int e   = tid + l * 256;
            const int row = e >> 4;
            const int d4  = (e & 15) << 2;
            float4 kv = *(const float4*)(Kg + row * 64 + d4);
            Ks[(d4 + 0) * AP + row] = kv.x;
            Ks[(d4 + 1) * AP + row] = kv.y;
            Ks[(d4 + 2) * AP + row] = kv.z;
            Ks[(d4 + 3) * AP + row] = kv.w;
            *(float4*)(Vs + row * AP + d4) = *(const float4*)(Vg + row * 64 + d4);
        }
        __syncthreads();

        // S = Q K^T  (4x4 per thread)
        float s[4][4];
#pragma unroll
        for (int r = 0; r < 4; ++r)
#pragma unroll
            for (int c = 0; c < 4; ++c) s[r][c] = 0.0f;

#pragma unroll 16
        for (int d = 0; d < 64; ++d) {
            float4 q4 = *(const float4*)(Qs + d * AP + i * 4);
            float4 k4 = *(const float4*)(Ks + d * AP + j * 4);
            float qa[4] = {q4.x, q4.y, q4.z, q4.w};
            float kb[4] = {k4.x, k4.y, k4.z, k4.w};
#pragma unroll
            for (int r = 0; r < 4; ++r)
#pragma unroll
                for (int c = 0; c < 4; ++c)
                    s[r][c] += qa[r] * kb[c];
        }

        const float sc = 0.125f;  // 1/sqrt(64)
        if (kt == qt) {
#pragma unroll
            for (int r = 0; r < 4; ++r)
#pragma unroll
                for (int c = 0; c < 4; ++c)
                    s[r][c] = ((j * 4 + c) <= (i * 4 + r)) ? s[r][c] * sc : -1e30f;
        } else {
#pragma unroll
            for (int r = 0; r < 4; ++r)
#pragma unroll
                for (int c = 0; c < 4; ++c)
                    s[r][c] *= sc;
        }

        // online softmax (row stats reduced over the 16 j-threads)
#pragma unroll
        for (int r = 0; r < 4; ++r) {
            float mx = fmaxf(fmaxf(s[r][0], s[r][1]), fmaxf(s[r][2], s[r][3]));
            mx = fmaxf(mx, __shfl_xor_sync(0xffffffffu, mx, 1));
            mx = fmaxf(mx, __shfl_xor_sync(0xffffffffu, mx, 2));
            mx = fmaxf(mx, __shfl_xor_sync(0xffffffffu, mx, 4));
            mx = fmaxf(mx, __shfl_xor_sync(0xffffffffu, mx, 8));
            const float mn   = fmaxf(mrow[r], mx);
            const float corr = __expf(mrow[r] - mn);
            mrow[r] = mn;
            float rs = 0.0f;
#pragma unroll
            for (int c = 0; c < 4; ++c) {
                float p = __expf(s[r][c] - mn);
                s[r][c] = p;
                rs += p;
            }
            rs += __shfl_xor_sync(0xffffffffu, rs, 1);
            rs += __shfl_xor_sync(0xffffffffu, rs, 2);
            rs += __shfl_xor_sync(0xffffffffu, rs, 4);
            rs += __shfl_xor_sync(0xffffffffu, rs, 8);
            lsum[r] = lsum[r] * corr + rs;
#pragma unroll
            for (int c = 0; c < 4; ++c) o[r][c] *= corr;
        }

        // stage P transposed: Ps[c][m]
#pragma unroll
        for (int c = 0; c < 4; ++c)
#pragma unroll
            for (int r = 0; r < 4; ++r)
                Ps[(j * 4 + c) * AP + i * 4 + r] = s[r][c];
        __syncthreads();

        // O += P V   (rows i*4.., dims j*4..)
#pragma unroll 16
        for (int c = 0; c < 64; ++c) {
            float4 p4 = *(const float4*)(Ps + c * AP + i * 4);
            float4 v4 = *(const float4*)(Vs + c * AP + j * 4);
            float pa[4] = {p4.x, p4.y, p4.z, p4.w};
            float vb[4] = {v4.x, v4.y, v4.z, v4.w};
#pragma unroll
            for (int r = 0; r < 4; ++r)
#pragma unroll
                for (int cc = 0; cc < 4; ++cc)
                    o[r][cc] += pa[r] * vb[cc];
        }
    }

    // write out, merging heads: Y[b, t, h*64 + d]
    const int b = bh >> 4;
    const int h = bh & 15;
#pragma unroll
    for (int r = 0; r < 4; ++r) {
        const float inv = 1.0f / lsum[r];
        const int t = qt * 64 + i * 4 + r;
        float4 outv = make_float4(o[r][0] * inv, o[r][1] * inv,
                                  o[r][2] * inv, o[r][3] * inv);
        *(float4*)(Y + (b * SEQ + t) * D_MODEL + h * 64 + j * 4) = outv;
    }
}

// ---------------------------------------------------------------------------
extern "C" void kernel_launch(void* const* d_in, const int* in_sizes, int n_in,
                              void* d_out, int out_size)
{
    const float* x  = (const float*)d_in[0];
    const float* Wk = (const float*)d_in[1];
    const float* bk = (const float*)d_in[2];
    const float* Wq = (const float*)d_in[3];
    const float* bq = (const float*)d_in[4];
    const float* Wv = (const float*)d_in[5];
    const float* bv = (const float*)d_in[6];
    const float* Wp = (const float*)d_in[7];
    const float* bp = (const float*)d_in[8];

    float *qp, *kp, *vp, *yp;
    cudaGetSymbolAddress((void**)&qp, g_q);
    cudaGetSymbolAddress((void**)&kp, g_k);
    cudaGetSymbolAddress((void**)&vp, g_v);
    cudaGetSymbolAddress((void**)&yp, g_y);

    const int attn_smem = 4 * 64 * AP * (int)sizeof(float);  // 69632 B
    cudaFuncSetAttribute(attn_kernel,
                         cudaFuncAttributeMaxDynamicSharedMemorySize, attn_smem);

    dim3 ggrid(D_MODEL / 128, M_ROWS / 128);   // (8, 32)
    sgemm_nt<<<ggrid, 256>>>(x, Wq, bq, qp, M_ROWS, D_MODEL, D_MODEL, 1);
    sgemm_nt<<<ggrid, 256>>>(x, Wk, bk, kp, M_ROWS, D_MODEL, D_MODEL, 1);
    sgemm_nt<<<ggrid, 256>>>(x, Wv, bv, vp, M_ROWS, D_MODEL, D_MODEL, 1);

    attn_kernel<<<dim3(SEQ / 64, BATCH * N_HEADS), 256, attn_smem>>>(qp, kp, vp, yp);

    sgemm_nt<<<ggrid, 256>>>(yp, Wp, bp, (float*)d_out, M_ROWS, D_MODEL, D_MODEL, 0);
}